// round 15
// baseline (speedup 1.0000x reference)
#include <cuda_runtime.h>
#include <cuda_fp16.h>
#include <cstdint>
#include <math.h>

// ---------------------------------------------------------------------------
// Luong 'general' attention, B=16, T=S=E=D=1024.
// Out: [h_tilde | attn_weights | attn_energies] fp32.
// GEMMs: mma.sync m16n8k16 fp16 hi/lo split, fp32 acc.
//   Stages 1,2 (3-term): K-chunk 32, hi/lo interleaved 128B rows, 96KB, 2 CTA/SM
//   Stages 4,5 (1-term): K-chunk 64, plain 128B rows,            96KB, 2 CTA/SM
// Block 128x128, 8 warps (2x4), warp tile 64x32, SW128 smem,
// 3-stage cp.async pipeline. Fused enc split+transpose prep kernel.
// ---------------------------------------------------------------------------

typedef __half hf;

#define BATCH 16
#define TDIM 1024
#define SDIM 1024
#define EDIM 1024
#define DDIM 1024
#define NBT (16 * 1024 * 1024)

__device__ __align__(256) hf g_enc_h[NBT],  g_enc_l[NBT];
__device__ __align__(256) hf g_encT_h[NBT];
__device__ __align__(256) hf g_hid_h[NBT],  g_hid_l[NBT];
__device__ __align__(256) hf g_proj_h[NBT], g_proj_l[NBT];
__device__ __align__(256) hf g_wts_h[NBT];
__device__ __align__(256) hf g_ctx_h[NBT];
__device__ __align__(256) hf g_wa_h[1024 * 1024], g_wa_l[1024 * 1024];
__device__ __align__(256) hf g_wo_h[1024 * 2048];

// ------------------------------ PTX helpers --------------------------------
__device__ __forceinline__ uint32_t smem_u32(const void* p) {
    uint32_t a;
    asm("{ .reg .u64 t; cvta.to.shared.u64 t, %1; cvt.u32.u64 %0, t; }"
        : "=r"(a) : "l"(p));
    return a;
}
__device__ __forceinline__ uint32_t swz(uint32_t off) {  // SW128: 128B rows
    return off ^ ((off >> 3) & 0x70);
}

#define CP_ASYNC16(saddr, gptr) \
    asm volatile("cp.async.cg.shared.global [%0], [%1], 16;" \
                 :: "r"(saddr), "l"(gptr) : "memory")
#define CP_COMMIT() asm volatile("cp.async.commit_group;" ::: "memory")
#define CP_WAITN(n) asm volatile("cp.async.wait_group %0;" :: "n"(n) : "memory")

#define LDSM4(r0, r1, r2, r3, addr) \
    asm volatile("ldmatrix.sync.aligned.m8n8.x4.shared.b16 {%0,%1,%2,%3}, [%4];" \
                 : "=r"(r0), "=r"(r1), "=r"(r2), "=r"(r3) : "r"(addr))

#define MMA16816(d, a, b0, b1) \
    asm volatile("mma.sync.aligned.m16n8k16.row.col.f32.f16.f16.f32 " \
                 "{%0,%1,%2,%3}, {%4,%5,%6,%7}, {%8,%9}, {%0,%1,%2,%3};" \
                 : "+f"((d)[0]), "+f"((d)[1]), "+f"((d)[2]), "+f"((d)[3]) \
                 : "r"((a)[0]), "r"((a)[1]), "r"((a)[2]), "r"((a)[3]), \
                   "r"(b0), "r"(b1))

__device__ __forceinline__ uint32_t packh(hf a, hf b) {
    __half2 t; t.x = a; t.y = b;
    return *reinterpret_cast<uint32_t*>(&t);
}

// ------------------------------ GEMM kernel --------------------------------
// NT=3: K-chunk 32, row r = [Xh 64B | Xl 64B] interleaved; A 16K + B 16K = 32KB.
// NT=1: K-chunk 64, plain 128B rows;            A 16K + B 16K = 32KB.
// Both: 3-stage pipeline = 96KB smem, 2 CTAs/SM.
template<int NT> struct BufCfg;
template<> struct BufCfg<3> { static const int BUF = 32768; static const int KC = 32; };
template<> struct BufCfg<1> { static const int BUF = 32768; static const int KC = 64; };
#define GSMEM (3 * 32768)

template<int NT>
__device__ __forceinline__ void stage_loads(
    uint32_t sbuf, const hf* pah, const hf* pal, const hf* pbh, const hf* pbl,
    int bm, int bn, int ldA, int ldB, int k0, int tid)
{
    #pragma unroll
    for (int j = 0; j < 4; ++j) {
        const int idx = tid + j * 256;
        const int r = idx >> 3, g = idx & 7;
        const uint32_t so = swz((uint32_t)(r * 128 + g * 16));
        if (NT == 3) {
            // g<4 -> hi bytes (g*16), g>=4 -> lo bytes ((g-4)*16)
            const hf* pa = (g & 4) ? pal : pah;
            const hf* pb = (g & 4) ? pbl : pbh;
            const size_t ko = (size_t)k0 + (g & 3) * 8;
            CP_ASYNC16(sbuf + so,         pa + (size_t)(bm + r) * ldA + ko);
            CP_ASYNC16(sbuf + 16384 + so, pb + (size_t)(bn + r) * ldB + ko);
        } else {
            CP_ASYNC16(sbuf + so,         pah + (size_t)(bm + r) * ldA + k0 + g * 8);
            CP_ASYNC16(sbuf + 16384 + so, pbh + (size_t)(bn + r) * ldB + k0 + g * 8);
        }
    }
}

// EPI: 0 = f32 store, 1 = bias + fp16 split (h+l), 2 = fp16 h-only, 3 = tanh f32
template<int EPI, int NT>
__global__ void __launch_bounds__(256, 2)
mma_gemm(const hf* __restrict__ Ah, const hf* __restrict__ Al,
         const hf* __restrict__ Bh, const hf* __restrict__ Bl,
         const hf* __restrict__ A2h, const hf* __restrict__ A2l,
         const hf* __restrict__ B2h, const hf* __restrict__ B2l,
         const float* __restrict__ bias,
         float* __restrict__ Cf, hf* __restrict__ Ch, hf* __restrict__ Cl,
         int NC1, int NC2, int lda, int ldb, int lda2, int ldb2, int ldc,
         long long sA, long long sB, long long sC)
{
    extern __shared__ char smem[];
    const uint32_t sb = smem_u32(smem);
    const int tid  = threadIdx.x;
    const int wid  = tid >> 5;
    const int lane = tid & 31;
    const long long z = blockIdx.z;
    Ah += z * sA; Al += z * sA; Bh += z * sB; Bl += z * sB;
    if (EPI == 0 || EPI == 3) Cf += z * sC;
    else { Ch += z * sC; Cl += z * sC; }

    const int bm = blockIdx.y * 128;
    const int bn = blockIdx.x * 128;
    const int wm = (wid >> 2) * 64;
    const int wn = (wid & 3) * 32;

    float acc[4][4][4];
    #pragma unroll
    for (int i = 0; i < 4; i++)
        #pragma unroll
        for (int j = 0; j < 4; j++)
            #pragma unroll
            for (int q = 0; q < 4; q++) acc[i][j][q] = 0.0f;

    const int NC = NC1 + NC2;
    const int KC = BufCfg<NT>::KC;

    stage_loads<NT>(sb, Ah, Al, Bh, Bl, bm, bn, lda, ldb, 0, tid);
    CP_COMMIT();
    if (NC > 1) {
        if (1 < NC1) stage_loads<NT>(sb + BufCfg<NT>::BUF, Ah, Al, Bh, Bl, bm, bn, lda, ldb, KC, tid);
        else         stage_loads<NT>(sb + BufCfg<NT>::BUF, A2h, A2l, B2h, B2l, bm, bn, lda2, ldb2, 0, tid);
    }
    CP_COMMIT();

    for (int c = 0; c < NC; ++c) {
        CP_WAITN(1);
        __syncthreads();

        if (c + 2 < NC) {
            const int cn = c + 2;
            const uint32_t nb = sb + (uint32_t)(cn % 3) * BufCfg<NT>::BUF;
            if (cn < NC1)
                stage_loads<NT>(nb, Ah, Al, Bh, Bl, bm, bn, lda, ldb, cn * KC, tid);
            else
                stage_loads<NT>(nb, A2h, A2l, B2h, B2l, bm, bn, lda2, ldb2, (cn - NC1) * KC, tid);
            CP_COMMIT();
        }

        const uint32_t ab = sb + (uint32_t)(c % 3) * BufCfg<NT>::BUF;
        const uint32_t bb = ab + 16384;

        if (NT == 3) {
            // K-chunk 32: 2 ksteps; hi at row+[0,63], lo at row+[64,127]
            #pragma unroll
            for (int ks = 0; ks < 2; ++ks) {
                uint32_t bh[2][4], bl[2][4];
                const int brow = wn + (lane & 7) + ((lane >> 4) << 3);
                const int bkb  = ks * 32 + (((lane >> 3) & 1) << 4);
                #pragma unroll
                for (int nj = 0; nj < 2; ++nj) {
                    const uint32_t base = (uint32_t)((brow + nj * 16) * 128 + bkb);
                    LDSM4(bh[nj][0], bh[nj][1], bh[nj][2], bh[nj][3], bb + swz(base));
                    LDSM4(bl[nj][0], bl[nj][1], bl[nj][2], bl[nj][3], bb + swz(base + 64));
                }
                const int arow = wm + (lane & 15);
                const int akb  = ks * 32 + ((lane >> 4) << 4);
                #pragma unroll
                for (int mi = 0; mi < 4; ++mi) {
                    uint32_t ah[4], al[4];
                    const uint32_t base = (uint32_t)((arow + mi * 16) * 128 + akb);
                    LDSM4(ah[0], ah[1], ah[2], ah[3], ab + swz(base));
                    LDSM4(al[0], al[1], al[2], al[3], ab + swz(base + 64));
                    #pragma unroll
                    for (int o = 0; o < 4; ++o) {
                        const uint32_t b0h = bh[o >> 1][(o & 1) * 2];
                        const uint32_t b1h = bh[o >> 1][(o & 1) * 2 + 1];
                        const uint32_t b0l = bl[o >> 1][(o & 1) * 2];
                        const uint32_t b1l = bl[o >> 1][(o & 1) * 2 + 1];
                        MMA16816(acc[mi][o], ah, b0h, b1h);
                        MMA16816(acc[mi][o], ah, b0l, b1l);
                        MMA16816(acc[mi][o], al, b0h, b1h);
                    }
                }
            }
        } else {
            // K-chunk 64: 4 ksteps, hi-only
            #pragma unroll
            for (int ks = 0; ks < 4; ++ks) {
                uint32_t ah[4][4], bh[2][4];
                const int arow = wm + (lane & 15);
                const int akb  = ks * 32 + ((lane >> 4) << 4);
                #pragma unroll
                for (int mi = 0; mi < 4; ++mi) {
                    const uint32_t ad = ab + swz((uint32_t)((arow + mi * 16) * 128 + akb));
                    LDSM4(ah[mi][0], ah[mi][1], ah[mi][2], ah[mi][3], ad);
                }
                const int brow = wn + (lane & 7) + ((lane >> 4) << 3);
                const int bkb  = ks * 32 + (((lane >> 3) & 1) << 4);
                #pragma unroll
                for (int nj = 0; nj < 2; ++nj) {
                    const uint32_t bd = bb + swz((uint32_t)((brow + nj * 16) * 128 + bkb));
                    LDSM4(bh[nj][0], bh[nj][1], bh[nj][2], bh[nj][3], bd);
                }
                #pragma unroll
                for (int mi = 0; mi < 4; ++mi)
                    #pragma unroll
                    for (int o = 0; o < 4; ++o)
                        MMA16816(acc[mi][o], ah[mi],
                                 bh[o >> 1][(o & 1) * 2], bh[o >> 1][(o & 1) * 2 + 1]);
            }
        }
    }

    // ------------------------------- epilogue ------------------------------
    const int rbase = bm + wm + (lane >> 2);
    const int cbase = bn + wn + (lane & 3) * 2;
    #pragma unroll
    for (int mi = 0; mi < 4; ++mi) {
        #pragma unroll
        for (int o = 0; o < 4; ++o) {
            const long long r0 = rbase + mi * 16;
            const int col = cbase + o * 8;
            float c0 = acc[mi][o][0], c1 = acc[mi][o][1];
            float c2 = acc[mi][o][2], c3 = acc[mi][o][3];
            if (EPI == 1) {
                const float bv0 = __ldg(bias + col), bv1 = __ldg(bias + col + 1);
                c0 += bv0; c1 += bv1; c2 += bv0; c3 += bv1;
            }
            if (EPI == 3) {
                c0 = tanhf(c0); c1 = tanhf(c1); c2 = tanhf(c2); c3 = tanhf(c3);
            }
            if (EPI == 0 || EPI == 3) {
                *(float2*)(Cf + r0 * ldc + col)       = make_float2(c0, c1);
                *(float2*)(Cf + (r0 + 8) * ldc + col) = make_float2(c2, c3);
            } else {
                hf h0 = __float2half_rn(c0), h1 = __float2half_rn(c1);
                hf h2 = __float2half_rn(c2), h3 = __float2half_rn(c3);
                *(uint32_t*)(Ch + r0 * ldc + col)       = packh(h0, h1);
                *(uint32_t*)(Ch + (r0 + 8) * ldc + col) = packh(h2, h3);
                if (EPI == 1) {
                    hf l0 = __float2half_rn(c0 - __half2float(h0));
                    hf l1 = __float2half_rn(c1 - __half2float(h1));
                    hf l2 = __float2half_rn(c2 - __half2float(h2));
                    hf l3 = __float2half_rn(c3 - __half2float(h3));
                    *(uint32_t*)(Cl + r0 * ldc + col)       = packh(l0, l1);
                    *(uint32_t*)(Cl + (r0 + 8) * ldc + col) = packh(l2, l3);
                }
            }
        }
    }
}

// --------------------------- auxiliary kernels -----------------------------
__global__ void __launch_bounds__(256)
split_k(const float4* __restrict__ x, uint2* __restrict__ h,
        uint2* __restrict__ l, int n4)
{
    const int i = blockIdx.x * 256 + threadIdx.x;
    if (i >= n4) return;
    const float4 v = x[i];
    hf h0 = __float2half_rn(v.x), h1 = __float2half_rn(v.y);
    hf h2 = __float2half_rn(v.z), h3 = __float2half_rn(v.w);
    hf l0 = __float2half_rn(v.x - __half2float(h0));
    hf l1 = __float2half_rn(v.y - __half2float(h1));
    hf l2 = __float2half_rn(v.z - __half2float(h2));
    hf l3 = __float2half_rn(v.w - __half2float(h3));
    h[i] = make_uint2(packh(h0, h1), packh(h2, h3));
    l[i] = make_uint2(packh(l0, l1), packh(l2, l3));
}

// hi-only fp16 conversion
__global__ void __launch_bounds__(256)
cvt_k(const float4* __restrict__ x, uint2* __restrict__ h, int n4)
{
    const int i = blockIdx.x * 256 + threadIdx.x;
    if (i >= n4) return;
    const float4 v = x[i];
    h[i] = make_uint2(packh(__float2half_rn(v.x), __float2half_rn(v.y)),
                      packh(__float2half_rn(v.z), __float2half_rn(v.w)));
}

// Fused: enc -> enc_h, enc_l (linear) + encT_h (transposed). One read of enc.
__global__ void __launch_bounds__(256)
splitT_k(const float* __restrict__ x, hf* __restrict__ xh, hf* __restrict__ xl,
         hf* __restrict__ th)
{
    __shared__ float t[32][33];
    const long long z = blockIdx.z;
    const float* xp = x  + z * (long long)SDIM * EDIM;
    hf* hp  = xh + z * (long long)SDIM * EDIM;
    hf* lp  = xl + z * (long long)SDIM * EDIM;
    hf* tp  = th + z * (long long)EDIM * SDIM;
    const int e0 = blockIdx.x * 32, s0 = blockIdx.y * 32;
    const int tx = threadIdx.x & 31, ty = threadIdx.x >> 5;
    #pragma unroll
    for (int j = 0; j < 4; ++j) {
        const long long o = (long long)(s0 + ty + 8 * j) * EDIM + e0 + tx;
        const float v = xp[o];
        t[ty + 8 * j][tx] = v;
        const hf h = __float2half_rn(v);
        hp[o] = h;
        lp[o] = __float2half_rn(v - __half2float(h));
    }
    __syncthreads();
    #pragma unroll
    for (int j = 0; j < 4; ++j) {
        const float v = t[tx][ty + 8 * j];
        tp[(long long)(e0 + ty + 8 * j) * SDIM + s0 + tx] = __float2half_rn(v);
    }
}

// row softmax (S=1024): fp32 weights out + fp16 hi
__global__ void __launch_bounds__(256)
softmax_sp(const float* __restrict__ E, float* __restrict__ W,
           hf* __restrict__ Wh)
{
    __shared__ float red[8];
    const long long row = blockIdx.x;
    const float4* e = (const float4*)(E + (row << 10));
    float4* w = (float4*)(W + (row << 10));
    const int t = threadIdx.x;

    float4 v = e[t];
    float m = fmaxf(fmaxf(v.x, v.y), fmaxf(v.z, v.w));
    #pragma unroll
    for (int o = 16; o; o >>= 1) m = fmaxf(m, __shfl_xor_sync(0xffffffffu, m, o));
    if ((t & 31) == 0) red[t >> 5] = m;
    __syncthreads();
    m = red[0];
    #pragma unroll
    for (int i = 1; i < 8; i++) m = fmaxf(m, red[i]);
    __syncthreads();

    float e0 = expf(v.x - m), e1 = expf(v.y - m);
    float e2 = expf(v.z - m), e3 = expf(v.w - m);
    float s = e0 + e1 + e2 + e3;
    #pragma unroll
    for (int o = 16; o; o >>= 1) s += __shfl_xor_sync(0xffffffffu, s, o);
    if ((t & 31) == 0) red[t >> 5] = s;
    __syncthreads();
    s = red[0] + red[1] + red[2] + red[3] + red[4] + red[5] + red[6] + red[7];

    const float inv = 1.0f / s;
    const float w0 = e0 * inv, w1 = e1 * inv, w2 = e2 * inv, w3 = e3 * inv;
    w[t] = make_float4(w0, w1, w2, w3);
    ((uint2*)(Wh + (row << 10)))[t] = make_uint2(
        packh(__float2half_rn(w0), __float2half_rn(w1)),
        packh(__float2half_rn(w2), __float2half_rn(w3)));
}

// -------------------------------- launcher ---------------------------------
extern "C" void kernel_launch(void* const* d_in, const int* in_sizes, int n_in,
                              void* d_out, int out_size)
{
    const float* hidden = (const float*)d_in[0];
    const float* enc    = (const float*)d_in[1];
    const float* Wa     = (const float*)d_in[2];
    const float* ba     = (const float*)d_in[3];
    const float* Wo     = (const float*)d_in[4];

    float* out = (float*)d_out;
    const long long SZ = (long long)NBT;
    float* htilde = out;
    float* wts    = out + SZ;
    float* enrg   = out + 2 * SZ;

    hf *enc_h, *enc_l, *encT_h, *hid_h, *hid_l, *proj_h, *proj_l;
    hf *wts_h, *ctx_h, *wa_h, *wa_l, *wo_h;
    cudaGetSymbolAddress((void**)&enc_h,  g_enc_h);  cudaGetSymbolAddress((void**)&enc_l,  g_enc_l);
    cudaGetSymbolAddress((void**)&encT_h, g_encT_h);
    cudaGetSymbolAddress((void**)&hid_h,  g_hid_h);  cudaGetSymbolAddress((void**)&hid_l,  g_hid_l);
    cudaGetSymbolAddress((void**)&proj_h, g_proj_h); cudaGetSymbolAddress((void**)&proj_l, g_proj_l);
    cudaGetSymbolAddress((void**)&wts_h,  g_wts_h);
    cudaGetSymbolAddress((void**)&ctx_h,  g_ctx_h);
    cudaGetSymbolAddress((void**)&wa_h,   g_wa_h);   cudaGetSymbolAddress((void**)&wa_l,   g_wa_l);
    cudaGetSymbolAddress((void**)&wo_h,   g_wo_h);

    cudaFuncSetAttribute(mma_gemm<1, 3>, cudaFuncAttributeMaxDynamicSharedMemorySize, GSMEM);
    cudaFuncSetAttribute(mma_gemm<0, 3>, cudaFuncAttributeMaxDynamicSharedMemorySize, GSMEM);
    cudaFuncSetAttribute(mma_gemm<2, 1>, cudaFuncAttributeMaxDynamicSharedMemorySize, GSMEM);
    cudaFuncSetAttribute(mma_gemm<3, 1>, cudaFuncAttributeMaxDynamicSharedMemorySize, GSMEM);

    // operand prep
    splitT_k<<<dim3(EDIM / 32, SDIM / 32, BATCH), 256>>>(enc, enc_h, enc_l, encT_h);
    split_k<<<NBT / 4 / 256, 256>>>((const float4*)hidden, (uint2*)hid_h, (uint2*)hid_l, NBT / 4);
    split_k<<<1024, 256>>>((const float4*)Wa, (uint2*)wa_h, (uint2*)wa_l, 1024 * 1024 / 4);
    cvt_k<<<2048, 256>>>((const float4*)Wo, (uint2*)wo_h, 1024 * 2048 / 4);

    // Stage 1: proj = enc @ Wa^T + ba -> fp16 split (3-term, K-chunk 32)
    mma_gemm<1, 3><<<dim3(DDIM / 128, (BATCH * SDIM) / 128, 1), 256, GSMEM>>>(
        enc_h, enc_l, wa_h, wa_l, nullptr, nullptr, nullptr, nullptr, ba,
        nullptr, proj_h, proj_l, EDIM / 32, 0, EDIM, EDIM, 0, 0, DDIM, 0, 0, 0);

    // Stage 2: energies = hidden @ proj^T (batched, 3-term, K-chunk 32) -> fp32
    mma_gemm<0, 3><<<dim3(SDIM / 128, TDIM / 128, BATCH), 256, GSMEM>>>(
        hid_h, hid_l, proj_h, proj_l, nullptr, nullptr, nullptr, nullptr, nullptr,
        enrg, nullptr, nullptr, DDIM / 32, 0, DDIM, DDIM, 0, 0, SDIM,
        (long long)TDIM * DDIM, (long long)SDIM * DDIM, (long long)TDIM * SDIM);

    // Stage 3: softmax -> fp32 weights + fp16 hi
    softmax_sp<<<BATCH * TDIM, 256>>>(enrg, wts, wts_h);

    // Stage 4: ctx = wts_h @ encT_h^T (batched, 1-term) -> fp16 hi
    mma_gemm<2, 1><<<dim3(EDIM / 128, TDIM / 128, BATCH), 256, GSMEM>>>(
        wts_h, nullptr, encT_h, nullptr, nullptr, nullptr, nullptr, nullptr, nullptr,
        nullptr, ctx_h, nullptr, SDIM / 64, 0, SDIM, SDIM, 0, 0, EDIM,
        (long long)TDIM * SDIM, (long long)EDIM * SDIM, (long long)TDIM * EDIM);

    // Stage 5: h_tilde = tanh(ctx @ Wo[:, :E]^T + hidden @ Wo[:, E:]^T)  (1-term)
    mma_gemm<3, 1><<<dim3(DDIM / 128, (BATCH * TDIM) / 128, 1), 256, GSMEM>>>(
        ctx_h, nullptr, wo_h, nullptr, hid_h, nullptr, wo_h + EDIM, nullptr, nullptr,
        htilde, nullptr, nullptr, EDIM / 64, DDIM / 64,
        EDIM, EDIM + DDIM, DDIM, EDIM + DDIM, DDIM, 0, 0, 0);
}

// round 17
// speedup vs baseline: 1.0165x; 1.0165x over previous
#include <cuda_runtime.h>
#include <cuda_fp16.h>
#include <cstdint>
#include <math.h>

// ---------------------------------------------------------------------------
// Luong 'general' attention, B=16, T=S=E=D=1024.
// Out: [h_tilde | attn_weights | attn_energies] fp32.
// GEMMs: mma.sync m16n8k16 fp16 hi/lo split, fp32 acc.
//   Stage 1 (proj):      3-term   Stage 2 (energies): 3-term  (192KB, 1 CTA/SM)
//   Stage 4 (ctx):       1-term   Stage 5 (h_tilde):  1-term  ( 96KB, 2 CTA/SM)
// Block 128x128, 8 warps (2x4), warp tile 64x32, K-chunk 64, SW128 smem,
// 3-stage cp.async pipeline. Wide-store fused enc split+transpose prep.
// ---------------------------------------------------------------------------

typedef __half hf;

#define BATCH 16
#define TDIM 1024
#define SDIM 1024
#define EDIM 1024
#define DDIM 1024
#define NBT (16 * 1024 * 1024)

__device__ __align__(256) hf g_enc_h[NBT],  g_enc_l[NBT];
__device__ __align__(256) hf g_encT_h[NBT];
__device__ __align__(256) hf g_hid_h[NBT],  g_hid_l[NBT];
__device__ __align__(256) hf g_proj_h[NBT], g_proj_l[NBT];
__device__ __align__(256) hf g_wts_h[NBT];
__device__ __align__(256) hf g_ctx_h[NBT];
__device__ __align__(256) hf g_wa_h[1024 * 1024], g_wa_l[1024 * 1024];
__device__ __align__(256) hf g_wo_h[1024 * 2048];

// ------------------------------ PTX helpers --------------------------------
__device__ __forceinline__ uint32_t smem_u32(const void* p) {
    uint32_t a;
    asm("{ .reg .u64 t; cvta.to.shared.u64 t, %1; cvt.u32.u64 %0, t; }"
        : "=r"(a) : "l"(p));
    return a;
}
__device__ __forceinline__ uint32_t swz(uint32_t off) {  // SW128: 128B rows
    return off ^ ((off >> 3) & 0x70);
}

#define CP_ASYNC16(saddr, gptr) \
    asm volatile("cp.async.cg.shared.global [%0], [%1], 16;" \
                 :: "r"(saddr), "l"(gptr) : "memory")
#define CP_COMMIT() asm volatile("cp.async.commit_group;" ::: "memory")
#define CP_WAITN(n) asm volatile("cp.async.wait_group %0;" :: "n"(n) : "memory")

#define LDSM4(r0, r1, r2, r3, addr) \
    asm volatile("ldmatrix.sync.aligned.m8n8.x4.shared.b16 {%0,%1,%2,%3}, [%4];" \
                 : "=r"(r0), "=r"(r1), "=r"(r2), "=r"(r3) : "r"(addr))

#define MMA16816(d, a, b0, b1) \
    asm volatile("mma.sync.aligned.m16n8k16.row.col.f32.f16.f16.f32 " \
                 "{%0,%1,%2,%3}, {%4,%5,%6,%7}, {%8,%9}, {%0,%1,%2,%3};" \
                 : "+f"((d)[0]), "+f"((d)[1]), "+f"((d)[2]), "+f"((d)[3]) \
                 : "r"((a)[0]), "r"((a)[1]), "r"((a)[2]), "r"((a)[3]), \
                   "r"(b0), "r"(b1))

__device__ __forceinline__ uint32_t packh(hf a, hf b) {
    __half2 t; t.x = a; t.y = b;
    return *reinterpret_cast<uint32_t*>(&t);
}

// ------------------------------ GEMM kernel --------------------------------
// NT=3 buffer (64KB): [Ah 16K][Al 16K][Bh 16K][Bl 16K]  -> 3-stage = 192KB
// NT=1 buffer (32KB): [Ah 16K][Bh 16K]                  -> 3-stage =  96KB, 2 CTA/SM
template<int NT> struct BufCfg;
template<> struct BufCfg<3> { static const int BUF = 65536; static const int BOFF = 32768; static const int OCC = 1; };
template<> struct BufCfg<1> { static const int BUF = 32768; static const int BOFF = 16384; static const int OCC = 2; };

template<int NT>
__device__ __forceinline__ void stage_loads(
    uint32_t sbuf, const hf* pah, const hf* pal, const hf* pbh, const hf* pbl,
    int bm, int bn, int ldA, int ldB, int k0, int tid)
{
    #pragma unroll
    for (int j = 0; j < 4; ++j) {
        const int idx = tid + j * 256;
        const int r = idx >> 3, g = idx & 7;
        const uint32_t so = swz((uint32_t)(r * 128 + g * 16));
        const size_t ao = (size_t)(bm + r) * ldA + k0 + g * 8;
        const size_t bo = (size_t)(bn + r) * ldB + k0 + g * 8;
        CP_ASYNC16(sbuf + so, pah + ao);
        if (NT == 3) CP_ASYNC16(sbuf + 16384 + so, pal + ao);
        CP_ASYNC16(sbuf + BufCfg<NT>::BOFF + so, pbh + bo);
        if (NT == 3) CP_ASYNC16(sbuf + 49152 + so, pbl + bo);
    }
}

// EPI: 0 = f32 store, 1 = bias + fp16 split (h+l), 2 = fp16 h-only, 3 = tanh f32
template<int EPI, int NT>
__global__ void __launch_bounds__(256, BufCfg<NT>::OCC)
mma_gemm(const hf* __restrict__ Ah, const hf* __restrict__ Al,
         const hf* __restrict__ Bh, const hf* __restrict__ Bl,
         const hf* __restrict__ A2h, const hf* __restrict__ A2l,
         const hf* __restrict__ B2h, const hf* __restrict__ B2l,
         const float* __restrict__ bias,
         float* __restrict__ Cf, hf* __restrict__ Ch, hf* __restrict__ Cl,
         int NC1, int NC2, int lda, int ldb, int lda2, int ldb2, int ldc,
         long long sA, long long sB, long long sC)
{
    extern __shared__ char smem[];
    const uint32_t sb = smem_u32(smem);
    const int tid  = threadIdx.x;
    const int wid  = tid >> 5;
    const int lane = tid & 31;
    const long long z = blockIdx.z;
    Ah += z * sA; Al += z * sA; Bh += z * sB; Bl += z * sB;
    if (EPI == 0 || EPI == 3) Cf += z * sC;
    else { Ch += z * sC; Cl += z * sC; }

    const int bm = blockIdx.y * 128;
    const int bn = blockIdx.x * 128;
    const int wm = (wid >> 2) * 64;
    const int wn = (wid & 3) * 32;

    float acc[4][4][4];
    #pragma unroll
    for (int i = 0; i < 4; i++)
        #pragma unroll
        for (int j = 0; j < 4; j++)
            #pragma unroll
            for (int q = 0; q < 4; q++) acc[i][j][q] = 0.0f;

    const int NC = NC1 + NC2;

    stage_loads<NT>(sb, Ah, Al, Bh, Bl, bm, bn, lda, ldb, 0, tid);
    CP_COMMIT();
    if (NC > 1) {
        if (1 < NC1) stage_loads<NT>(sb + BufCfg<NT>::BUF, Ah, Al, Bh, Bl, bm, bn, lda, ldb, 64, tid);
        else         stage_loads<NT>(sb + BufCfg<NT>::BUF, A2h, A2l, B2h, B2l, bm, bn, lda2, ldb2, 0, tid);
    }
    CP_COMMIT();

    for (int c = 0; c < NC; ++c) {
        CP_WAITN(1);
        __syncthreads();

        if (c + 2 < NC) {
            const int cn = c + 2;
            const uint32_t nb = sb + (uint32_t)(cn % 3) * BufCfg<NT>::BUF;
            if (cn < NC1)
                stage_loads<NT>(nb, Ah, Al, Bh, Bl, bm, bn, lda, ldb, cn * 64, tid);
            else
                stage_loads<NT>(nb, A2h, A2l, B2h, B2l, bm, bn, lda2, ldb2, (cn - NC1) * 64, tid);
            CP_COMMIT();
        }

        const uint32_t ab = sb + (uint32_t)(c % 3) * BufCfg<NT>::BUF;
        const uint32_t bb = ab + BufCfg<NT>::BOFF;

        #pragma unroll
        for (int ks = 0; ks < 4; ++ks) {
            uint32_t ah[4][4], al[4][4], bh[2][4], bl[2][4];
            const int arow = wm + (lane & 15);
            const int akb  = ks * 32 + ((lane >> 4) << 4);
            #pragma unroll
            for (int mi = 0; mi < 4; ++mi) {
                const uint32_t ad = ab + swz((uint32_t)((arow + mi * 16) * 128 + akb));
                LDSM4(ah[mi][0], ah[mi][1], ah[mi][2], ah[mi][3], ad);
                if (NT == 3) LDSM4(al[mi][0], al[mi][1], al[mi][2], al[mi][3], ad + 16384);
            }
            const int brow = wn + (lane & 7) + ((lane >> 4) << 3);
            const int bkb  = ks * 32 + (((lane >> 3) & 1) << 4);
            #pragma unroll
            for (int nj = 0; nj < 2; ++nj) {
                const uint32_t bd = bb + swz((uint32_t)((brow + nj * 16) * 128 + bkb));
                LDSM4(bh[nj][0], bh[nj][1], bh[nj][2], bh[nj][3], bd);
                if (NT == 3) LDSM4(bl[nj][0], bl[nj][1], bl[nj][2], bl[nj][3], bd + 16384);
            }
            #pragma unroll
            for (int mi = 0; mi < 4; ++mi)
                #pragma unroll
                for (int o = 0; o < 4; ++o)
                    MMA16816(acc[mi][o], ah[mi],
                             bh[o >> 1][(o & 1) * 2], bh[o >> 1][(o & 1) * 2 + 1]);
            if (NT == 3) {
                #pragma unroll
                for (int mi = 0; mi < 4; ++mi)
                    #pragma unroll
                    for (int o = 0; o < 4; ++o)
                        MMA16816(acc[mi][o], ah[mi],
                                 bl[o >> 1][(o & 1) * 2], bl[o >> 1][(o & 1) * 2 + 1]);
                #pragma unroll
                for (int mi = 0; mi < 4; ++mi)
                    #pragma unroll
                    for (int o = 0; o < 4; ++o)
                        MMA16816(acc[mi][o], al[mi],
                                 bh[o >> 1][(o & 1) * 2], bh[o >> 1][(o & 1) * 2 + 1]);
            }
        }
    }

    // ------------------------------- epilogue ------------------------------
    const int rbase = bm + wm + (lane >> 2);
    const int cbase = bn + wn + (lane & 3) * 2;
    #pragma unroll
    for (int mi = 0; mi < 4; ++mi) {
        #pragma unroll
        for (int o = 0; o < 4; ++o) {
            const long long r0 = rbase + mi * 16;
            const int col = cbase + o * 8;
            float c0 = acc[mi][o][0], c1 = acc[mi][o][1];
            float c2 = acc[mi][o][2], c3 = acc[mi][o][3];
            if (EPI == 1) {
                const float bv0 = __ldg(bias + col), bv1 = __ldg(bias + col + 1);
                c0 += bv0; c1 += bv1; c2 += bv0; c3 += bv1;
            }
            if (EPI == 3) {
                c0 = tanhf(c0); c1 = tanhf(c1); c2 = tanhf(c2); c3 = tanhf(c3);
            }
            if (EPI == 0 || EPI == 3) {
                *(float2*)(Cf + r0 * ldc + col)       = make_float2(c0, c1);
                *(float2*)(Cf + (r0 + 8) * ldc + col) = make_float2(c2, c3);
            } else {
                hf h0 = __float2half_rn(c0), h1 = __float2half_rn(c1);
                hf h2 = __float2half_rn(c2), h3 = __float2half_rn(c3);
                *(uint32_t*)(Ch + r0 * ldc + col)       = packh(h0, h1);
                *(uint32_t*)(Ch + (r0 + 8) * ldc + col) = packh(h2, h3);
                if (EPI == 1) {
                    hf l0 = __float2half_rn(c0 - __half2float(h0));
                    hf l1 = __float2half_rn(c1 - __half2float(h1));
                    hf l2 = __float2half_rn(c2 - __half2float(h2));
                    hf l3 = __float2half_rn(c3 - __half2float(h3));
                    *(uint32_t*)(Cl + r0 * ldc + col)       = packh(l0, l1);
                    *(uint32_t*)(Cl + (r0 + 8) * ldc + col) = packh(l2, l3);
                }
            }
        }
    }
}

// --------------------------- auxiliary kernels -----------------------------
__global__ void __launch_bounds__(256)
split_k(const float4* __restrict__ x, uint2* __restrict__ h,
        uint2* __restrict__ l, int n4)
{
    const int i = blockIdx.x * 256 + threadIdx.x;
    if (i >= n4) return;
    const float4 v = x[i];
    hf h0 = __float2half_rn(v.x), h1 = __float2half_rn(v.y);
    hf h2 = __float2half_rn(v.z), h3 = __float2half_rn(v.w);
    hf l0 = __float2half_rn(v.x - __half2float(h0));
    hf l1 = __float2half_rn(v.y - __half2float(h1));
    hf l2 = __float2half_rn(v.z - __half2float(h2));
    hf l3 = __float2half_rn(v.w - __half2float(h3));
    h[i] = make_uint2(packh(h0, h1), packh(h2, h3));
    l[i] = make_uint2(packh(l0, l1), packh(l2, l3));
}

// hi-only fp16 conversion
__global__ void __launch_bounds__(256)
cvt_k(const float4* __restrict__ x, uint2* __restrict__ h, int n4)
{
    const int i = blockIdx.x * 256 + threadIdx.x;
    if (i >= n4) return;
    const float4 v = x[i];
    h[i] = make_uint2(packh(__float2half_rn(v.x), __float2half_rn(v.y)),
                      packh(__float2half_rn(v.z), __float2half_rn(v.w)));
}

// Fused wide-store: enc -> enc_h, enc_l (linear, half2 stores) + encT_h
// (transposed, half2 stores). Tile 64e x 32s, one read of enc.
// Tile layout: t[e][s], e in 0..63, s in 0..31.
__global__ void __launch_bounds__(256)
splitT_k(const float* __restrict__ x, hf* __restrict__ xh, hf* __restrict__ xl,
         hf* __restrict__ th)
{
    __shared__ float t[64][33];
    const long long z = blockIdx.z;
    const float* xp = x  + z * (long long)SDIM * EDIM;
    hf* hp  = xh + z * (long long)SDIM * EDIM;
    hf* lp  = xl + z * (long long)SDIM * EDIM;
    hf* tp  = th + z * (long long)EDIM * SDIM;
    const int e0 = blockIdx.x * 64, s0 = blockIdx.y * 32;

    // Phase 1: load 64e x 32s as float2 along e. tx = e-pair (0..31), ty = s (0..7 x4)
    const int tx = threadIdx.x & 31, ty = threadIdx.x >> 5;
    #pragma unroll
    for (int j = 0; j < 4; ++j) {
        const int s = ty + 8 * j;                              // 0..31
        const long long o = (long long)(s0 + s) * EDIM + e0 + 2 * tx;
        const float2 v = *(const float2*)(xp + o);
        t[2 * tx][s]     = v.x;                                // t[e][s]
        t[2 * tx + 1][s] = v.y;
        const hf h0 = __float2half_rn(v.x), h1 = __float2half_rn(v.y);
        *(uint32_t*)(hp + o) = packh(h0, h1);
        *(uint32_t*)(lp + o) = packh(__float2half_rn(v.x - __half2float(h0)),
                                     __float2half_rn(v.y - __half2float(h1)));
    }
    __syncthreads();

    // Phase 2: transposed store, pairs along s. sy = s-pair (0..15), ey = e (0..15 x4)
    const int sy = threadIdx.x & 15;                           // s-pair index
    const int ey = threadIdx.x >> 4;                           // 0..15
    #pragma unroll
    for (int j = 0; j < 4; ++j) {
        const int e = ey + 16 * j;                             // 0..63
        const float v0 = t[e][2 * sy];
        const float v1 = t[e][2 * sy + 1];
        *(uint32_t*)(tp + (long long)(e0 + e) * SDIM + s0 + 2 * sy) =
            packh(__float2half_rn(v0), __float2half_rn(v1));
    }
}

// row softmax (S=1024): fp32 weights out + fp16 hi
__global__ void __launch_bounds__(256)
softmax_sp(const float* __restrict__ E, float* __restrict__ W,
           hf* __restrict__ Wh)
{
    __shared__ float red[8];
    const long long row = blockIdx.x;
    const float4* e = (const float4*)(E + (row << 10));
    float4* w = (float4*)(W + (row << 10));
    const int t = threadIdx.x;

    float4 v = e[t];
    float m = fmaxf(fmaxf(v.x, v.y), fmaxf(v.z, v.w));
    #pragma unroll
    for (int o = 16; o; o >>= 1) m = fmaxf(m, __shfl_xor_sync(0xffffffffu, m, o));
    if ((t & 31) == 0) red[t >> 5] = m;
    __syncthreads();
    m = red[0];
    #pragma unroll
    for (int i = 1; i < 8; i++) m = fmaxf(m, red[i]);
    __syncthreads();

    float e0 = expf(v.x - m), e1 = expf(v.y - m);
    float e2 = expf(v.z - m), e3 = expf(v.w - m);
    float s = e0 + e1 + e2 + e3;
    #pragma unroll
    for (int o = 16; o; o >>= 1) s += __shfl_xor_sync(0xffffffffu, s, o);
    if ((t & 31) == 0) red[t >> 5] = s;
    __syncthreads();
    s = red[0] + red[1] + red[2] + red[3] + red[4] + red[5] + red[6] + red[7];

    const float inv = 1.0f / s;
    const float w0 = e0 * inv, w1 = e1 * inv, w2 = e2 * inv, w3 = e3 * inv;
    w[t] = make_float4(w0, w1, w2, w3);
    ((uint2*)(Wh + (row << 10)))[t] = make_uint2(
        packh(__float2half_rn(w0), __float2half_rn(w1)),
        packh(__float2half_rn(w2), __float2half_rn(w3)));
}

// -------------------------------- launcher ---------------------------------
extern "C" void kernel_launch(void* const* d_in, const int* in_sizes, int n_in,
                              void* d_out, int out_size)
{
    const float* hidden = (const float*)d_in[0];
    const float* enc    = (const float*)d_in[1];
    const float* Wa     = (const float*)d_in[2];
    const float* ba     = (const float*)d_in[3];
    const float* Wo     = (const float*)d_in[4];

    float* out = (float*)d_out;
    const long long SZ = (long long)NBT;
    float* htilde = out;
    float* wts    = out + SZ;
    float* enrg   = out + 2 * SZ;

    hf *enc_h, *enc_l, *encT_h, *hid_h, *hid_l, *proj_h, *proj_l;
    hf *wts_h, *ctx_h, *wa_h, *wa_l, *wo_h;
    cudaGetSymbolAddress((void**)&enc_h,  g_enc_h);  cudaGetSymbolAddress((void**)&enc_l,  g_enc_l);
    cudaGetSymbolAddress((void**)&encT_h, g_encT_h);
    cudaGetSymbolAddress((void**)&hid_h,  g_hid_h);  cudaGetSymbolAddress((void**)&hid_l,  g_hid_l);
    cudaGetSymbolAddress((void**)&proj_h, g_proj_h); cudaGetSymbolAddress((void**)&proj_l, g_proj_l);
    cudaGetSymbolAddress((void**)&wts_h,  g_wts_h);
    cudaGetSymbolAddress((void**)&ctx_h,  g_ctx_h);
    cudaGetSymbolAddress((void**)&wa_h,   g_wa_h);   cudaGetSymbolAddress((void**)&wa_l,   g_wa_l);
    cudaGetSymbolAddress((void**)&wo_h,   g_wo_h);

    const int SMEM3 = 3 * BufCfg<3>::BUF;   // 192KB
    const int SMEM1 = 3 * BufCfg<1>::BUF;   //  96KB
    cudaFuncSetAttribute(mma_gemm<1, 3>, cudaFuncAttributeMaxDynamicSharedMemorySize, SMEM3);
    cudaFuncSetAttribute(mma_gemm<0, 3>, cudaFuncAttributeMaxDynamicSharedMemorySize, SMEM3);
    cudaFuncSetAttribute(mma_gemm<2, 1>, cudaFuncAttributeMaxDynamicSharedMemorySize, SMEM1);
    cudaFuncSetAttribute(mma_gemm<3, 1>, cudaFuncAttributeMaxDynamicSharedMemorySize, SMEM1);

    // operand prep
    splitT_k<<<dim3(EDIM / 64, SDIM / 32, BATCH), 256>>>(enc, enc_h, enc_l, encT_h);
    split_k<<<NBT / 4 / 256, 256>>>((const float4*)hidden, (uint2*)hid_h, (uint2*)hid_l, NBT / 4);
    split_k<<<1024, 256>>>((const float4*)Wa, (uint2*)wa_h, (uint2*)wa_l, 1024 * 1024 / 4);
    cvt_k<<<2048, 256>>>((const float4*)Wo, (uint2*)wo_h, 1024 * 2048 / 4);

    // Stage 1: proj = enc @ Wa^T + ba -> fp16 split (3-term)
    mma_gemm<1, 3><<<dim3(DDIM / 128, (BATCH * SDIM) / 128, 1), 256, SMEM3>>>(
        enc_h, enc_l, wa_h, wa_l, nullptr, nullptr, nullptr, nullptr, ba,
        nullptr, proj_h, proj_l, EDIM / 64, 0, EDIM, EDIM, 0, 0, DDIM, 0, 0, 0);

    // Stage 2: energies = hidden @ proj^T (batched, 3-term) -> fp32
    mma_gemm<0, 3><<<dim3(SDIM / 128, TDIM / 128, BATCH), 256, SMEM3>>>(
        hid_h, hid_l, proj_h, proj_l, nullptr, nullptr, nullptr, nullptr, nullptr,
        enrg, nullptr, nullptr, DDIM / 64, 0, DDIM, DDIM, 0, 0, SDIM,
        (long long)TDIM * DDIM, (long long)SDIM * DDIM, (long long)TDIM * SDIM);

    // Stage 3: softmax -> fp32 weights + fp16 hi
    softmax_sp<<<BATCH * TDIM, 256>>>(enrg, wts, wts_h);

    // Stage 4: ctx = wts_h @ encT_h^T (batched, 1-term, 2 CTA/SM) -> fp16 hi
    mma_gemm<2, 1><<<dim3(EDIM / 128, TDIM / 128, BATCH), 256, SMEM1>>>(
        wts_h, nullptr, encT_h, nullptr, nullptr, nullptr, nullptr, nullptr, nullptr,
        nullptr, ctx_h, nullptr, SDIM / 64, 0, SDIM, SDIM, 0, 0, EDIM,
        (long long)TDIM * SDIM, (long long)EDIM * SDIM, (long long)TDIM * EDIM);

    // Stage 5: h_tilde = tanh(ctx @ Wo[:, :E]^T + hidden @ Wo[:, E:]^T)  (1-term, 2 CTA/SM)
    mma_gemm<3, 1><<<dim3(DDIM / 128, (BATCH * TDIM) / 128, 1), 256, SMEM1>>>(
        ctx_h, nullptr, wo_h, nullptr, hid_h, nullptr, wo_h + EDIM, nullptr, nullptr,
        htilde, nullptr, nullptr, EDIM / 64, DDIM / 64,
        EDIM, EDIM + DDIM, DDIM, EDIM + DDIM, DDIM, 0, 0, 0);
}